// round 13
// baseline (speedup 1.0000x reference)
#include <cuda_runtime.h>
#include <cuda_fp16.h>
#include <cstdint>

#define NN   50000
#define NE   800000
#define H    128
#define NG   500
#define NBLK 49            // scan blocks: 49*1024 >= 50001
#define SROW 528

// ---------------- device scratch ----------------
__device__ float   g_h[NN * H];          // fp32 node features (agg accumulated in place)
__device__ __half  g_hh_hi[NN * H];      // fp16 split of h (GEMM A input)
__device__ __half  g_hh_lo[NN * H];
__device__ float   g_ac[NN * 256];       // per node: A(128)|C(128) fp32
__device__ float   g_bdf[NN * 256];      // per node interleaved: B[c],D[c] fp32 pairs
__device__ __half  g_ea[NE * 64];        // per CSR slot: 32 hi halves | 32 lo halves
__device__ uint4   g_wnp[64 * 8 * 32];   // node weight frags
__device__ uint4   g_wep[32 * 2 * 32];   // edge weight frags
__device__ float   g_bA[128], g_bC[128];
__device__ int     g_off[NN + 1];
__device__ int     g_cursor[NN];
__device__ int     g_src[NE];            // CSR: src per slot
__device__ int     g_dst[NE];            // CSR: dst per slot
__device__ int     g_eid[NE];            // CSR: original edge id (used by k_econv only)
__device__ int     g_bsum[NBLK], g_bpre[NBLK];
__device__ float   g_pool[NG * H];
__device__ float   g_cnt[NG];

// ---------------- helpers ----------------
__device__ __forceinline__ void mma16816(float* c, uint32_t a0, uint32_t a1,
                                         uint32_t a2, uint32_t a3,
                                         uint32_t b0, uint32_t b1) {
    asm volatile("mma.sync.aligned.m16n8k16.row.col.f32.f16.f16.f32 "
                 "{%0,%1,%2,%3}, {%4,%5,%6,%7}, {%8,%9}, {%0,%1,%2,%3};"
                 : "+f"(c[0]), "+f"(c[1]), "+f"(c[2]), "+f"(c[3])
                 : "r"(a0), "r"(a1), "r"(a2), "r"(a3), "r"(b0), "r"(b1));
}
__device__ __forceinline__ uint4 ldg_cs(const uint4* p) { return __ldcs(p); }

// ---------------- init / CSR ----------------
__global__ void k_zero() {
    int i = blockIdx.x * blockDim.x + threadIdx.x;
    if (i <= NN)     g_off[i] = 0;
    if (i <  NN)     g_cursor[i] = 0;
    if (i <  NG * H) g_pool[i] = 0.f;
    if (i <  NG)     g_cnt[i] = 0.f;
}

__global__ void k_embed(const int* __restrict__ x, const float* __restrict__ emb) {
    int idx = blockIdx.x * blockDim.x + threadIdx.x;
    if (idx >= NN * H) return;
    int i = idx >> 7, c = idx & (H - 1);
    float v = emb[x[i] * H + c];
    g_h[idx] = v;
    __half hi = __float2half(v);
    g_hh_hi[idx] = hi;
    g_hh_lo[idx] = __float2half(v - __half2float(hi));
}

__global__ void k_count(const int* __restrict__ ei) {
    int e = blockIdx.x * blockDim.x + threadIdx.x;
    if (e < NE) atomicAdd(&g_off[ei[NE + e] + 1], 1);
}

__global__ void k_scan1() {
    __shared__ int s[1024];
    int i = blockIdx.x * 1024 + threadIdx.x;
    int v = (i <= NN) ? g_off[i] : 0;
    s[threadIdx.x] = v;
    __syncthreads();
    #pragma unroll
    for (int d = 1; d < 1024; d <<= 1) {
        int t = (threadIdx.x >= d) ? s[threadIdx.x - d] : 0;
        __syncthreads();
        s[threadIdx.x] += t;
        __syncthreads();
    }
    if (i <= NN) g_off[i] = s[threadIdx.x];
    if (threadIdx.x == 1023) g_bsum[blockIdx.x] = s[1023];
}

__global__ void k_scan2() {
    if (threadIdx.x == 0) {
        int run = 0;
        for (int b = 0; b < NBLK; b++) { g_bpre[b] = run; run += g_bsum[b]; }
    }
}

__global__ void k_scan3() {
    int i = blockIdx.x * 1024 + threadIdx.x;
    if (blockIdx.x > 0 && i <= NN) g_off[i] += g_bpre[blockIdx.x];
}

__global__ void k_scatter(const int* __restrict__ ei) {
    int e = blockIdx.x * blockDim.x + threadIdx.x;
    if (e >= NE) return;
    int s = ei[e], d = ei[NE + e];
    int p = g_off[d] + atomicAdd(&g_cursor[d], 1);
    g_src[p] = s;
    g_dst[p] = d;
    g_eid[p] = e;
}

// eattr fp32 -> split fp16, written in CSR slot order (runs after k_scatter)
__global__ void k_econv(const float* __restrict__ eattr) {
    int idx = blockIdx.x * blockDim.x + threadIdx.x;
    if (idx >= NE * 4) return;
    int r = idx >> 2, c8 = (idx & 3) * 8;
    int eid = g_eid[r];
    const float* s = eattr + (size_t)eid * 32 + c8;
    float4 f0 = *(const float4*)s;
    float4 f1 = *(const float4*)(s + 4);
    float fv[8] = {f0.x, f0.y, f0.z, f0.w, f1.x, f1.y, f1.z, f1.w};
    __half hv[8], lv[8];
    #pragma unroll
    for (int j = 0; j < 8; j++) {
        hv[j] = __float2half(fv[j]);
        lv[j] = __float2half(fv[j] - __half2float(hv[j]));
    }
    *(uint4*)(g_ea + (size_t)r * 64 + c8)      = *(uint4*)hv;
    *(uint4*)(g_ea + (size_t)r * 64 + 32 + c8) = *(uint4*)lv;
}

// ---------------- weight pack: fragment-major, split fp16 ----------------
__device__ __forceinline__ float nodeW(const float* Wf, const float* Ws, int n, int k) {
    if (n < 128)      return Wf[(128 + k) * H + n];
    else if (n < 256) return Ws[(128 + k) * H + (n - 128)];
    else if (n < 384) return Wf[k * H + (n - 256)];
    else              return Ws[k * H + (n - 384)];
}

__global__ void k_pack(const float* __restrict__ Wf, const float* __restrict__ bf,
                       const float* __restrict__ Ws, const float* __restrict__ bs) {
    int idx = blockIdx.x * blockDim.x + threadIdx.x;
    if (idx < 65536) {                       // node frags: t(64) ks(8) lane(32) w(4)
        int w = idx & 3, lane = (idx >> 2) & 31, ks = (idx >> 7) & 7, t = idx >> 10;
        int r = w & 1, hilo = w >> 1;
        int n = t * 8 + (lane >> 2);
        int k0 = ks * 16 + (lane & 3) * 2 + r * 8;
        float v0 = nodeW(Wf, Ws, n, k0);
        float v1 = nodeW(Wf, Ws, n, k0 + 1);
        __half h0 = __float2half(v0), h1 = __float2half(v1);
        __half2 out;
        if (hilo == 0) out = __halves2half2(h0, h1);
        else out = __halves2half2(__float2half(v0 - __half2float(h0)),
                                  __float2half(v1 - __half2float(h1)));
        ((uint32_t*)g_wnp)[idx] = *(uint32_t*)&out;
    } else if (idx < 65536 + 8192) {         // edge frags: t(32) ks(2) lane(32) w(4)
        int i2 = idx - 65536;
        int w = i2 & 3, lane = (i2 >> 2) & 31, ks = (i2 >> 7) & 1, t = i2 >> 8;
        int r = w & 1, hilo = w >> 1;
        int n = t * 8 + (lane >> 2);
        int k0 = ks * 16 + (lane & 3) * 2 + r * 8;
        float v0, v1;
        if (n < 128) { v0 = Wf[(256 + k0) * H + n]; v1 = Wf[(256 + k0 + 1) * H + n]; }
        else         { v0 = Ws[(256 + k0) * H + n - 128]; v1 = Ws[(256 + k0 + 1) * H + n - 128]; }
        __half h0 = __float2half(v0), h1 = __float2half(v1);
        __half2 out;
        if (hilo == 0) out = __halves2half2(h0, h1);
        else out = __halves2half2(__float2half(v0 - __half2float(h0)),
                                  __float2half(v1 - __half2float(h1)));
        ((uint32_t*)g_wep)[i2] = *(uint32_t*)&out;
    } else if (idx < 65536 + 8192 + 256) {
        int c = idx - (65536 + 8192);
        if (c < 128) g_bA[c] = bf[c];
        else         g_bC[c - 128] = bs[c - 128];
    }
}

// ---------------- node GEMM (split-fp16 3-pass HMMA, frag-packed B) ----------------
__global__ __launch_bounds__(256) void gemm_node() {
    extern __shared__ __half sm[];
    __half* sH = sm;                 // 128 x 136
    __half* sL = sm + 128 * 136;
    int tid = threadIdx.x;
    int m0 = blockIdx.x * 128;

    for (int i = tid; i < 4096; i += 256) {
        int half_sel = i >> 11;
        int r = (i >> 4) & 127, c = i & 15;
        uint4 v = make_uint4(0, 0, 0, 0);
        if (m0 + r < NN) {
            const __half* src = half_sel ? g_hh_lo : g_hh_hi;
            v = *(const uint4*)(src + (size_t)(m0 + r) * 128 + c * 8);
        }
        __half* dstp = half_sel ? sL : sH;
        *(uint4*)(dstp + r * 136 + c * 8) = v;
    }
    __syncthreads();

    int w = tid >> 5, lane = tid & 31;
    int g = lane >> 2, tig = lane & 3;
    int row_l = w * 16 + g;
    int grow0 = m0 + row_l, grow1 = grow0 + 8;

    for (int q = 0; q < 8; q++) {
        float acc[8][4];
        #pragma unroll
        for (int i = 0; i < 8; i++)
            #pragma unroll
            for (int j = 0; j < 4; j++) acc[i][j] = 0.f;

        #pragma unroll
        for (int ks = 0; ks < 8; ks++) {
            const __half* apH = sH + row_l * 136 + ks * 16 + tig * 2;
            const __half* apL = sL + row_l * 136 + ks * 16 + tig * 2;
            uint32_t aH0 = *(const uint32_t*)apH;
            uint32_t aH1 = *(const uint32_t*)(apH + 8 * 136);
            uint32_t aH2 = *(const uint32_t*)(apH + 8);
            uint32_t aH3 = *(const uint32_t*)(apH + 8 * 136 + 8);
            uint32_t aL0 = *(const uint32_t*)apL;
            uint32_t aL1 = *(const uint32_t*)(apL + 8 * 136);
            uint32_t aL2 = *(const uint32_t*)(apL + 8);
            uint32_t aL3 = *(const uint32_t*)(apL + 8 * 136 + 8);
            #pragma unroll
            for (int i = 0; i < 8; i++) {
                int t = (q < 4) ? ((i < 4) ? (q * 4 + i) : (16 + q * 4 + i - 4))
                                : (32 + (q - 4) * 8 + i);
                uint4 f = g_wnp[(t * 8 + ks) * 32 + lane];
                mma16816(acc[i], aH0, aH1, aH2, aH3, f.x, f.y);
                mma16816(acc[i], aH0, aH1, aH2, aH3, f.z, f.w);
                mma16816(acc[i], aL0, aL1, aL2, aL3, f.x, f.y);
            }
        }

        if (q < 4) {       // B|D fp32 interleaved
            #pragma unroll
            for (int i = 0; i < 4; i++) {
                int col = q * 32 + i * 8 + tig * 2;
                if (grow0 < NN) {
                    float4 o = make_float4(acc[i][0], acc[i + 4][0], acc[i][1], acc[i + 4][1]);
                    *(float4*)(g_bdf + (size_t)grow0 * 256 + col * 2) = o;
                }
                if (grow1 < NN) {
                    float4 o = make_float4(acc[i][2], acc[i + 4][2], acc[i][3], acc[i + 4][3]);
                    *(float4*)(g_bdf + (size_t)grow1 * 256 + col * 2) = o;
                }
            }
        } else {           // A|C plain fp32
            #pragma unroll
            for (int i = 0; i < 8; i++) {
                int col = (q - 4) * 64 + i * 8 + tig * 2;
                if (grow0 < NN)
                    *(float2*)(g_ac + (size_t)grow0 * 256 + col) = make_float2(acc[i][0], acc[i][1]);
                if (grow1 < NN)
                    *(float2*)(g_ac + (size_t)grow1 * 256 + col) = make_float2(acc[i][2], acc[i][3]);
            }
        }
    }
}

// ---------------- fused edge GEMM + aggregation ----------------
__device__ __forceinline__ float gatef(float gf, float gs) {
    float sig = __fdividef(1.f, 1.f + __expf(-gf));
    float sp  = fmaxf(gs, 0.f) + __logf(1.f + __expf(-fabsf(gs)));
    return sig * sp;
}

#define SM_FUSED (2 * 128 * 40 * 2 + 128 * SROW)

__global__ __launch_bounds__(256) void k_fused() {
    extern __shared__ char smraw[];
    __half* sH = (__half*)smraw;                       // 128 x 40 halves
    __half* sL = (__half*)(smraw + 10240);
    char*  stage = smraw + 20480;                      // 128 x SROW
    int tid = threadIdx.x;
    int m0 = blockIdx.x * 128;

    // load A: 128 CSR rows x 128B (sequential, streaming)
    for (int i = tid; i < 1024; i += 256) {
        int r = i >> 3, seg = i & 7;
        uint4 v = ldg_cs((const uint4*)(g_ea + (size_t)(m0 + r) * 64 + seg * 8));
        if (seg < 4) *(uint4*)(sH + r * 40 + seg * 8) = v;
        else         *(uint4*)(sL + r * 40 + (seg - 4) * 8) = v;
    }
    __syncthreads();

    int w = tid >> 5, lane = tid & 31;
    int g = lane >> 2, tig = lane & 3;
    int row_l = w * 16 + g;

    for (int nh = 0; nh < 2; nh++) {
        float af[8][4], as_[8][4];
        #pragma unroll
        for (int i = 0; i < 8; i++)
            #pragma unroll
            for (int j = 0; j < 4; j++) { af[i][j] = 0.f; as_[i][j] = 0.f; }

        #pragma unroll
        for (int ks = 0; ks < 2; ks++) {
            const __half* apH = sH + row_l * 40 + ks * 16 + tig * 2;
            const __half* apL = sL + row_l * 40 + ks * 16 + tig * 2;
            uint32_t aH0 = *(const uint32_t*)apH;
            uint32_t aH1 = *(const uint32_t*)(apH + 8 * 40);
            uint32_t aH2 = *(const uint32_t*)(apH + 8);
            uint32_t aH3 = *(const uint32_t*)(apH + 8 * 40 + 8);
            uint32_t aL0 = *(const uint32_t*)apL;
            uint32_t aL1 = *(const uint32_t*)(apL + 8 * 40);
            uint32_t aL2 = *(const uint32_t*)(apL + 8);
            uint32_t aL3 = *(const uint32_t*)(apL + 8 * 40 + 8);
            #pragma unroll
            for (int p = 0; p < 8; p++) {
                int tf = nh * 8 + p;
                uint4 ff = g_wep[(tf * 2 + ks) * 32 + lane];
                uint4 fs = g_wep[((tf + 16) * 2 + ks) * 32 + lane];
                mma16816(af[p],  aH0, aH1, aH2, aH3, ff.x, ff.y);
                mma16816(af[p],  aH0, aH1, aH2, aH3, ff.z, ff.w);
                mma16816(af[p],  aL0, aL1, aL2, aL3, ff.x, ff.y);
                mma16816(as_[p], aH0, aH1, aH2, aH3, fs.x, fs.y);
                mma16816(as_[p], aH0, aH1, aH2, aH3, fs.z, fs.w);
                mma16816(as_[p], aL0, aL1, aL2, aL3, fs.x, fs.y);
            }
        }
        #pragma unroll
        for (int p = 0; p < 8; p++) {
            int cb = nh * 256 + p * 32 + tig * 8;
            __half2 o[2];
            o[0] = __floats2half2_rn(af[p][0], as_[p][0]);
            o[1] = __floats2half2_rn(af[p][1], as_[p][1]);
            *(uint2*)(stage + row_l * SROW + cb) = *(uint2*)o;
            o[0] = __floats2half2_rn(af[p][2], as_[p][2]);
            o[1] = __floats2half2_rn(af[p][3], as_[p][3]);
            *(uint2*)(stage + (row_l + 8) * SROW + cb) = *(uint2*)o;
        }
    }
    __syncthreads();

    // ---- aggregation: warp w owns slots [w*16, w*16+16) ----
    int base = w * 16;
    int c4 = lane * 4;
    float4 bAv = *(const float4*)&g_bA[c4];
    float4 bCv = *(const float4*)&g_bC[c4];
    float4 acc = make_float4(0.f, 0.f, 0.f, 0.f);
    float4 Av = acc, Cv = acc;
    int cur = -1;
    for (int j = 0; j < 16; j++) {
        int slot = m0 + base + j;
        int dst = g_dst[slot];
        int src = g_src[slot];
        if (dst != cur) {
            if (cur >= 0) {
                atomicAdd(&g_h[cur * H + c4 + 0], acc.x);
                atomicAdd(&g_h[cur * H + c4 + 1], acc.y);
                atomicAdd(&g_h[cur * H + c4 + 2], acc.z);
                atomicAdd(&g_h[cur * H + c4 + 3], acc.w);
            }
            Av = *(const float4*)&g_ac[(size_t)dst * 256 + c4];
            Cv = *(const float4*)&g_ac[(size_t)dst * 256 + 128 + c4];
            Av.x += bAv.x; Av.y += bAv.y; Av.z += bAv.z; Av.w += bAv.w;
            Cv.x += bCv.x; Cv.y += bCv.y; Cv.z += bCv.z; Cv.w += bCv.w;
            acc = make_float4(0.f, 0.f, 0.f, 0.f);
            cur = dst;
        }
        float4 bd0 = *(const float4*)(g_bdf + (size_t)src * 256 + c4 * 2);
        float4 bd1 = *(const float4*)(g_bdf + (size_t)src * 256 + c4 * 2 + 4);
        uint4 st = *(const uint4*)(stage + (base + j) * SROW + lane * 16);
        const __half2* ch = (const __half2*)&st;
        float2 c0 = __half22float2(ch[0]), c1 = __half22float2(ch[1]);
        float2 c2 = __half22float2(ch[2]), c3 = __half22float2(ch[3]);
        acc.x += gatef(Av.x + bd0.x + c0.x, Cv.x + bd0.y + c0.y);
        acc.y += gatef(Av.y + bd0.z + c1.x, Cv.y + bd0.w + c1.y);
        acc.z += gatef(Av.z + bd1.x + c2.x, Cv.z + bd1.y + c2.y);
        acc.w += gatef(Av.w + bd1.z + c3.x, Cv.w + bd1.w + c3.y);
    }
    if (cur >= 0) {
        atomicAdd(&g_h[cur * H + c4 + 0], acc.x);
        atomicAdd(&g_h[cur * H + c4 + 1], acc.y);
        atomicAdd(&g_h[cur * H + c4 + 2], acc.z);
        atomicAdd(&g_h[cur * H + c4 + 3], acc.w);
    }
}

// relu in place + regenerate fp16 splits
__global__ void k_hupdate() {
    int idx = blockIdx.x * blockDim.x + threadIdx.x;
    if (idx >= NN * H) return;
    float v = fmaxf(g_h[idx], 0.f);
    g_h[idx] = v;
    __half hi = __float2half(v);
    g_hh_hi[idx] = hi;
    g_hh_lo[idx] = __float2half(v - __half2float(hi));
}

// ---------------- pooling + final linear ----------------
__global__ void k_pool(const int* __restrict__ batch) {
    int idx = blockIdx.x * blockDim.x + threadIdx.x;
    if (idx >= NN * H) return;
    int i = idx >> 7, c = idx & (H - 1);
    atomicAdd(&g_pool[batch[i] * H + c], g_h[idx]);
}

__global__ void k_cnt(const int* __restrict__ batch) {
    int i = blockIdx.x * blockDim.x + threadIdx.x;
    if (i < NN) atomicAdd(&g_cnt[batch[i]], 1.f);
}

__global__ void k_final(const float* __restrict__ Wlin, const float* __restrict__ blin,
                        float* __restrict__ out) {
    __shared__ float p[H];
    int g = blockIdx.x, j = threadIdx.x;
    float cnt = fmaxf(g_cnt[g], 1.f);
    p[j] = g_pool[g * H + j] / cnt;
    __syncthreads();
    float s = blin[j];
    #pragma unroll 8
    for (int k = 0; k < H; k++) s = fmaf(p[k], Wlin[k * H + j], s);
    out[g * H + j] = s;
}

// ---------------- launch ----------------
extern "C" void kernel_launch(void* const* d_in, const int* in_sizes, int n_in,
                              void* d_out, int out_size) {
    const int*   x     = (const int*)d_in[0];
    const int*   ei    = (const int*)d_in[1];
    const float* eattr = (const float*)d_in[2];
    const int*   batch = (const int*)d_in[3];
    const float* emb   = (const float*)d_in[4];
    const float* Wf[3] = {(const float*)d_in[5],  (const float*)d_in[9],  (const float*)d_in[13]};
    const float* bf[3] = {(const float*)d_in[6],  (const float*)d_in[10], (const float*)d_in[14]};
    const float* Ws[3] = {(const float*)d_in[7],  (const float*)d_in[11], (const float*)d_in[15]};
    const float* bs[3] = {(const float*)d_in[8],  (const float*)d_in[12], (const float*)d_in[16]};
    const float* Wlin  = (const float*)d_in[17];
    const float* blin  = (const float*)d_in[18];
    float* out = (float*)d_out;

    static int smem_set = 0;
    if (!smem_set) {
        cudaFuncSetAttribute(gemm_node, cudaFuncAttributeMaxDynamicSharedMemorySize,
                             2 * 128 * 136 * (int)sizeof(__half));
        cudaFuncSetAttribute(k_fused, cudaFuncAttributeMaxDynamicSharedMemorySize, SM_FUSED);
        smem_set = 1;
    }

    // gemm_node at launch index 3 (the ncu capture slot)
    k_pack<<<(65536 + 8192 + 256 + 255) / 256, 256>>>(Wf[0], bf[0], Ws[0], bs[0]);   // 0
    k_embed<<<(NN * H + 255) / 256, 256>>>(x, emb);                                   // 1
    k_zero<<<(NG * H + 255) / 256, 256>>>();                                          // 2 (FULL grid: covers g_pool)
    gemm_node<<<(NN + 127) / 128, 256, 2 * 128 * 136 * sizeof(__half)>>>();           // 3 <- ncu
    k_count<<<(NE + 255) / 256, 256>>>(ei);                                           // 4
    k_scan1<<<NBLK, 1024>>>();
    k_scan2<<<1, 32>>>();
    k_scan3<<<NBLK, 1024>>>();
    k_scatter<<<(NE + 255) / 256, 256>>>(ei);
    k_econv<<<(NE * 4 + 255) / 256, 256>>>(eattr);
    k_fused<<<NE / 128, 256, SM_FUSED>>>();
    k_hupdate<<<(NN * H + 255) / 256, 256>>>();

    for (int l = 1; l < 3; l++) {
        k_pack<<<(65536 + 8192 + 256 + 255) / 256, 256>>>(Wf[l], bf[l], Ws[l], bs[l]);
        gemm_node<<<(NN + 127) / 128, 256, 2 * 128 * 136 * sizeof(__half)>>>();
        k_fused<<<NE / 128, 256, SM_FUSED>>>();
        k_hupdate<<<(NN * H + 255) / 256, 256>>>();
    }

    k_pool<<<(NN * H + 255) / 256, 256>>>(batch);
    k_cnt<<<(NN + 255) / 256, 256>>>(batch);
    k_final<<<NG, H>>>(Wlin, blin, out);
}

// round 14
// speedup vs baseline: 1.3179x; 1.3179x over previous
#include <cuda_runtime.h>
#include <cuda_fp16.h>
#include <cstdint>

#define NN   50000
#define NE   800000
#define H    128
#define NG   500
#define NBLK 49            // scan blocks: 49*1024 >= 50001
#define SROW 528

// ---------------- device scratch ----------------
__device__ float   g_h[NN * H];          // fp32 node features
__device__ __half  g_hh_hi[NN * H];      // fp16 split of h (GEMM A input)
__device__ __half  g_hh_lo[NN * H];
__device__ float   g_ac[NN * 256];       // per node: A(128)|C(128) fp32
__device__ float   g_bdf[NN * 256];      // per node interleaved: B[c],D[c] fp32 pairs
__device__ __half2 g_cc[NE * H];         // per CSR slot: half2(cf,cs)  (~410MB)
__device__ __half  g_ea[NE * 64];        // per CSR slot: 32 hi | 32 lo halves
__device__ uint4   g_wnp[64 * 8 * 32];   // node weight frags
__device__ uint4   g_wep[32 * 2 * 32];   // edge weight frags
__device__ float   g_bA[128], g_bC[128];
__device__ int     g_off[NN + 1];
__device__ int     g_cursor[NN];
__device__ int     g_src[NE];            // CSR: src per slot
__device__ int     g_eid[NE];            // CSR: original edge id (k_econv only)
__device__ int     g_bsum[NBLK], g_bpre[NBLK];
__device__ float   g_pool[NG * H];
__device__ float   g_cnt[NG];

// ---------------- helpers ----------------
__device__ __forceinline__ void mma16816(float* c, uint32_t a0, uint32_t a1,
                                         uint32_t a2, uint32_t a3,
                                         uint32_t b0, uint32_t b1) {
    asm volatile("mma.sync.aligned.m16n8k16.row.col.f32.f16.f16.f32 "
                 "{%0,%1,%2,%3}, {%4,%5,%6,%7}, {%8,%9}, {%0,%1,%2,%3};"
                 : "+f"(c[0]), "+f"(c[1]), "+f"(c[2]), "+f"(c[3])
                 : "r"(a0), "r"(a1), "r"(a2), "r"(a3), "r"(b0), "r"(b1));
}
__device__ __forceinline__ uint4 ldg_cs(const uint4* p) { return __ldcs(p); }
__device__ __forceinline__ void  stg_cs(uint4* p, uint4 v) { __stcs(p, v); }

// ---------------- init / CSR ----------------
__global__ void k_zero() {
    int i = blockIdx.x * blockDim.x + threadIdx.x;
    if (i <= NN)     g_off[i] = 0;
    if (i <  NN)     g_cursor[i] = 0;
    if (i <  NG * H) g_pool[i] = 0.f;
    if (i <  NG)     g_cnt[i] = 0.f;
}

__global__ void k_embed(const int* __restrict__ x, const float* __restrict__ emb) {
    int idx = blockIdx.x * blockDim.x + threadIdx.x;
    if (idx >= NN * H) return;
    int i = idx >> 7, c = idx & (H - 1);
    float v = emb[x[i] * H + c];
    g_h[idx] = v;
    __half hi = __float2half(v);
    g_hh_hi[idx] = hi;
    g_hh_lo[idx] = __float2half(v - __half2float(hi));
}

__global__ void k_count(const int* __restrict__ ei) {
    int e = blockIdx.x * blockDim.x + threadIdx.x;
    if (e < NE) atomicAdd(&g_off[ei[NE + e] + 1], 1);
}

__global__ void k_scan1() {
    __shared__ int s[1024];
    int i = blockIdx.x * 1024 + threadIdx.x;
    int v = (i <= NN) ? g_off[i] : 0;
    s[threadIdx.x] = v;
    __syncthreads();
    #pragma unroll
    for (int d = 1; d < 1024; d <<= 1) {
        int t = (threadIdx.x >= d) ? s[threadIdx.x - d] : 0;
        __syncthreads();
        s[threadIdx.x] += t;
        __syncthreads();
    }
    if (i <= NN) g_off[i] = s[threadIdx.x];
    if (threadIdx.x == 1023) g_bsum[blockIdx.x] = s[1023];
}

__global__ void k_scan2() {
    if (threadIdx.x == 0) {
        int run = 0;
        for (int b = 0; b < NBLK; b++) { g_bpre[b] = run; run += g_bsum[b]; }
    }
}

__global__ void k_scan3() {
    int i = blockIdx.x * 1024 + threadIdx.x;
    if (blockIdx.x > 0 && i <= NN) g_off[i] += g_bpre[blockIdx.x];
}

__global__ void k_scatter(const int* __restrict__ ei) {
    int e = blockIdx.x * blockDim.x + threadIdx.x;
    if (e >= NE) return;
    int s = ei[e], d = ei[NE + e];
    int p = g_off[d] + atomicAdd(&g_cursor[d], 1);
    g_src[p] = s;
    g_eid[p] = e;
}

// eattr fp32 -> split fp16, CSR slot order (runs after k_scatter)
__global__ void k_econv(const float* __restrict__ eattr) {
    int idx = blockIdx.x * blockDim.x + threadIdx.x;
    if (idx >= NE * 4) return;
    int r = idx >> 2, c8 = (idx & 3) * 8;
    int eid = g_eid[r];
    const float* s = eattr + (size_t)eid * 32 + c8;
    float4 f0 = *(const float4*)s;
    float4 f1 = *(const float4*)(s + 4);
    float fv[8] = {f0.x, f0.y, f0.z, f0.w, f1.x, f1.y, f1.z, f1.w};
    __half hv[8], lv[8];
    #pragma unroll
    for (int j = 0; j < 8; j++) {
        hv[j] = __float2half(fv[j]);
        lv[j] = __float2half(fv[j] - __half2float(hv[j]));
    }
    *(uint4*)(g_ea + (size_t)r * 64 + c8)      = *(uint4*)hv;
    *(uint4*)(g_ea + (size_t)r * 64 + 32 + c8) = *(uint4*)lv;
}

// ---------------- weight pack: fragment-major, split fp16 ----------------
__device__ __forceinline__ float nodeW(const float* Wf, const float* Ws, int n, int k) {
    if (n < 128)      return Wf[(128 + k) * H + n];
    else if (n < 256) return Ws[(128 + k) * H + (n - 128)];
    else if (n < 384) return Wf[k * H + (n - 256)];
    else              return Ws[k * H + (n - 384)];
}

__global__ void k_pack(const float* __restrict__ Wf, const float* __restrict__ bf,
                       const float* __restrict__ Ws, const float* __restrict__ bs) {
    int idx = blockIdx.x * blockDim.x + threadIdx.x;
    if (idx < 65536) {                       // node frags: t(64) ks(8) lane(32) w(4)
        int w = idx & 3, lane = (idx >> 2) & 31, ks = (idx >> 7) & 7, t = idx >> 10;
        int r = w & 1, hilo = w >> 1;
        int n = t * 8 + (lane >> 2);
        int k0 = ks * 16 + (lane & 3) * 2 + r * 8;
        float v0 = nodeW(Wf, Ws, n, k0);
        float v1 = nodeW(Wf, Ws, n, k0 + 1);
        __half h0 = __float2half(v0), h1 = __float2half(v1);
        __half2 out;
        if (hilo == 0) out = __halves2half2(h0, h1);
        else out = __halves2half2(__float2half(v0 - __half2float(h0)),
                                  __float2half(v1 - __half2float(h1)));
        ((uint32_t*)g_wnp)[idx] = *(uint32_t*)&out;
    } else if (idx < 65536 + 8192) {         // edge frags: t(32) ks(2) lane(32) w(4)
        int i2 = idx - 65536;
        int w = i2 & 3, lane = (i2 >> 2) & 31, ks = (i2 >> 7) & 1, t = i2 >> 8;
        int r = w & 1, hilo = w >> 1;
        int n = t * 8 + (lane >> 2);
        int k0 = ks * 16 + (lane & 3) * 2 + r * 8;
        float v0, v1;
        if (n < 128) { v0 = Wf[(256 + k0) * H + n]; v1 = Wf[(256 + k0 + 1) * H + n]; }
        else         { v0 = Ws[(256 + k0) * H + n - 128]; v1 = Ws[(256 + k0 + 1) * H + n - 128]; }
        __half h0 = __float2half(v0), h1 = __float2half(v1);
        __half2 out;
        if (hilo == 0) out = __halves2half2(h0, h1);
        else out = __halves2half2(__float2half(v0 - __half2float(h0)),
                                  __float2half(v1 - __half2float(h1)));
        ((uint32_t*)g_wep)[i2] = *(uint32_t*)&out;
    } else if (idx < 65536 + 8192 + 256) {
        int c = idx - (65536 + 8192);
        if (c < 128) g_bA[c] = bf[c];
        else         g_bC[c - 128] = bs[c - 128];
    }
}

// ---------------- node GEMM: smem-staged weight frags ----------------
// smem: A hi (34816B) | A lo (34816B) | W stage (32768B) = 102400B
#define SM_NODE (2 * 128 * 136 * 2 + 8 * 8 * 32 * 16)

__global__ __launch_bounds__(256) void gemm_node() {
    extern __shared__ char smn[];
    __half* sH = (__half*)smn;                      // 128 x 136
    __half* sL = (__half*)(smn + 34816);
    uint4*  sW = (uint4*)(smn + 69632);             // [i(8)][ks(8)][lane(32)]
    int tid = threadIdx.x;
    int m0 = blockIdx.x * 128;

    for (int i = tid; i < 4096; i += 256) {
        int half_sel = i >> 11;
        int r = (i >> 4) & 127, c = i & 15;
        uint4 v = make_uint4(0, 0, 0, 0);
        if (m0 + r < NN) {
            const __half* src = half_sel ? g_hh_lo : g_hh_hi;
            v = *(const uint4*)(src + (size_t)(m0 + r) * 128 + c * 8);
        }
        __half* dstp = half_sel ? sL : sH;
        *(uint4*)(dstp + r * 136 + c * 8) = v;
    }
    __syncthreads();

    int w = tid >> 5, lane = tid & 31;
    int g = lane >> 2, tig = lane & 3;
    int row_l = w * 16 + g;
    int grow0 = m0 + row_l, grow1 = grow0 + 8;

    for (int q = 0; q < 8; q++) {
        // stage this q-chunk's 8x8 fragment set into smem (coalesced, batched)
        #pragma unroll
        for (int rr = 0; rr < 8; rr++) {
            int j = tid + rr * 256;                 // 0..2047
            int i = j >> 8, ks = (j >> 5) & 7, ln = j & 31;
            int t = (q < 4) ? ((i < 4) ? (q * 4 + i) : (16 + q * 4 + i - 4))
                            : (32 + (q - 4) * 8 + i);
            sW[j] = g_wnp[(t * 8 + ks) * 32 + ln];
        }
        __syncthreads();

        float acc[8][4];
        #pragma unroll
        for (int i = 0; i < 8; i++)
            #pragma unroll
            for (int j = 0; j < 4; j++) acc[i][j] = 0.f;

        #pragma unroll
        for (int ks = 0; ks < 8; ks++) {
            const __half* apH = sH + row_l * 136 + ks * 16 + tig * 2;
            const __half* apL = sL + row_l * 136 + ks * 16 + tig * 2;
            uint32_t aH0 = *(const uint32_t*)apH;
            uint32_t aH1 = *(const uint32_t*)(apH + 8 * 136);
            uint32_t aH2 = *(const uint32_t*)(apH + 8);
            uint32_t aH3 = *(const uint32_t*)(apH + 8 * 136 + 8);
            uint32_t aL0 = *(const uint32_t*)apL;
            uint32_t aL1 = *(const uint32_t*)(apL + 8 * 136);
            uint32_t aL2 = *(const uint32_t*)(apL + 8);
            uint32_t aL3 = *(const uint32_t*)(apL + 8 * 136 + 8);
            #pragma unroll
            for (int i = 0; i < 8; i++) {
                uint4 f = sW[(i * 8 + ks) * 32 + lane];
                mma16816(acc[i], aH0, aH1, aH2, aH3, f.x, f.y);
                mma16816(acc[i], aH0, aH1, aH2, aH3, f.z, f.w);
                mma16816(acc[i], aL0, aL1, aL2, aL3, f.x, f.y);
            }
        }

        if (q < 4) {       // B|D fp32 interleaved
            #pragma unroll
            for (int i = 0; i < 4; i++) {
                int col = q * 32 + i * 8 + tig * 2;
                if (grow0 < NN) {
                    float4 o = make_float4(acc[i][0], acc[i + 4][0], acc[i][1], acc[i + 4][1]);
                    *(float4*)(g_bdf + (size_t)grow0 * 256 + col * 2) = o;
                }
                if (grow1 < NN) {
                    float4 o = make_float4(acc[i][2], acc[i + 4][2], acc[i][3], acc[i + 4][3]);
                    *(float4*)(g_bdf + (size_t)grow1 * 256 + col * 2) = o;
                }
            }
        } else {           // A|C plain fp32
            #pragma unroll
            for (int i = 0; i < 8; i++) {
                int col = (q - 4) * 64 + i * 8 + tig * 2;
                if (grow0 < NN)
                    *(float2*)(g_ac + (size_t)grow0 * 256 + col) = make_float2(acc[i][0], acc[i][1]);
                if (grow1 < NN)
                    *(float2*)(g_ac + (size_t)grow1 * 256 + col) = make_float2(acc[i][2], acc[i][3]);
            }
        }
        __syncthreads();   // protect sW before next chunk's overwrite
    }
}

// ---------------- edge GEMM: slot-ordered in/out, staged coalesced writeout ----------
__global__ __launch_bounds__(256) void gemm_edge() {
    __shared__ __half sH[64 * 40];
    __shared__ __half sL[64 * 40];
    __shared__ char  stage[64 * SROW];
    int tid = threadIdx.x;
    int m0 = blockIdx.x * 64;

    for (int i = tid; i < 512; i += 256) {       // 64 rows x 8 uint4
        int r = i >> 3, seg = i & 7;
        uint4 v = ldg_cs((const uint4*)(g_ea + (size_t)(m0 + r) * 64 + seg * 8));
        if (seg < 4) *(uint4*)(sH + r * 40 + seg * 8) = v;
        else         *(uint4*)(sL + r * 40 + (seg - 4) * 8) = v;
    }
    __syncthreads();

    int w = tid >> 5, lane = tid & 31;
    int mg = w >> 1, nh = w & 1;
    int g = lane >> 2, tig = lane & 3;
    int row_l = mg * 16 + g;

    float af[8][4], as_[8][4];
    #pragma unroll
    for (int i = 0; i < 8; i++)
        #pragma unroll
        for (int j = 0; j < 4; j++) { af[i][j] = 0.f; as_[i][j] = 0.f; }

    #pragma unroll
    for (int ks = 0; ks < 2; ks++) {
        const __half* apH = sH + row_l * 40 + ks * 16 + tig * 2;
        const __half* apL = sL + row_l * 40 + ks * 16 + tig * 2;
        uint32_t aH0 = *(const uint32_t*)apH;
        uint32_t aH1 = *(const uint32_t*)(apH + 8 * 40);
        uint32_t aH2 = *(const uint32_t*)(apH + 8);
        uint32_t aH3 = *(const uint32_t*)(apH + 8 * 40 + 8);
        uint32_t aL0 = *(const uint32_t*)apL;
        uint32_t aL1 = *(const uint32_t*)(apL + 8 * 40);
        uint32_t aL2 = *(const uint32_t*)(apL + 8);
        uint32_t aL3 = *(const uint32_t*)(apL + 8 * 40 + 8);
        #pragma unroll
        for (int p = 0; p < 8; p++) {
            int tf = nh * 8 + p;
            uint4 ff = g_wep[(tf * 2 + ks) * 32 + lane];
            uint4 fs = g_wep[((tf + 16) * 2 + ks) * 32 + lane];
            mma16816(af[p],  aH0, aH1, aH2, aH3, ff.x, ff.y);
            mma16816(af[p],  aH0, aH1, aH2, aH3, ff.z, ff.w);
            mma16816(af[p],  aL0, aL1, aL2, aL3, ff.x, ff.y);
            mma16816(as_[p], aH0, aH1, aH2, aH3, fs.x, fs.y);
            mma16816(as_[p], aH0, aH1, aH2, aH3, fs.z, fs.w);
            mma16816(as_[p], aL0, aL1, aL2, aL3, fs.x, fs.y);
        }
    }

    #pragma unroll
    for (int p = 0; p < 8; p++) {
        int cb = nh * 256 + p * 32 + tig * 8;
        __half2 o[2];
        o[0] = __floats2half2_rn(af[p][0], as_[p][0]);
        o[1] = __floats2half2_rn(af[p][1], as_[p][1]);
        *(uint2*)(stage + row_l * SROW + cb) = *(uint2*)o;
        o[0] = __floats2half2_rn(af[p][2], as_[p][2]);
        o[1] = __floats2half2_rn(af[p][3], as_[p][3]);
        *(uint2*)(stage + (row_l + 8) * SROW + cb) = *(uint2*)o;
    }
    __syncthreads();

    for (int i = tid; i < 2048; i += 256) {
        int row = i >> 5, seg = i & 31;
        uint4 v = *(const uint4*)(stage + row * SROW + seg * 16);
        stg_cs((uint4*)((char*)g_cc + (size_t)(m0 + row) * 512 + seg * 16), v);
    }
}

// ---------------- edge aggregation: one warp per dst node, slot-ordered g_cc -------
__device__ __forceinline__ float gatef(float gf, float gs) {
    float sig = __fdividef(1.f, 1.f + __expf(-gf));
    float sp  = fmaxf(gs, 0.f) + __logf(1.f + __expf(-fabsf(gs)));
    return sig * sp;
}

__global__ __launch_bounds__(256) void k_edge() {
    int w = (blockIdx.x * blockDim.x + threadIdx.x) >> 5;
    int lane = threadIdx.x & 31;
    if (w >= NN) return;
    int c4 = lane * 4;
    float4 acc = *(const float4*)&g_h[w * H + c4];
    float4 Av = *(const float4*)&g_ac[w * 256 + c4];
    float4 Cv = *(const float4*)&g_ac[w * 256 + 128 + c4];
    float4 bAv = *(const float4*)&g_bA[c4];
    float4 bCv = *(const float4*)&g_bC[c4];
    Av.x += bAv.x; Av.y += bAv.y; Av.z += bAv.z; Av.w += bAv.w;
    Cv.x += bCv.x; Cv.y += bCv.y; Cv.z += bCv.z; Cv.w += bCv.w;
    int e0 = g_off[w], e1 = g_off[w + 1];
    for (int e = e0; e < e1; e++) {
        int src = g_src[e];
        float4 bd0 = *(const float4*)(g_bdf + (size_t)src * 256 + c4 * 2);
        float4 bd1 = *(const float4*)(g_bdf + (size_t)src * 256 + c4 * 2 + 4);
        uint4 ccv = ldg_cs((const uint4*)(g_cc + (size_t)e * 128 + c4));  // sequential
        const __half2* ch = (const __half2*)&ccv;
        float2 c0 = __half22float2(ch[0]), c1 = __half22float2(ch[1]);
        float2 c2 = __half22float2(ch[2]), c3 = __half22float2(ch[3]);
        acc.x += gatef(Av.x + bd0.x + c0.x, Cv.x + bd0.y + c0.y);
        acc.y += gatef(Av.y + bd0.z + c1.x, Cv.y + bd0.w + c1.y);
        acc.z += gatef(Av.z + bd1.x + c2.x, Cv.z + bd1.y + c2.y);
        acc.w += gatef(Av.w + bd1.z + c3.x, Cv.w + bd1.w + c3.y);
    }
    acc.x = fmaxf(acc.x, 0.f);
    acc.y = fmaxf(acc.y, 0.f);
    acc.z = fmaxf(acc.z, 0.f);
    acc.w = fmaxf(acc.w, 0.f);
    *(float4*)&g_h[w * H + c4] = acc;
    __half hi[4], lo[4];
    hi[0] = __float2half(acc.x); lo[0] = __float2half(acc.x - __half2float(hi[0]));
    hi[1] = __float2half(acc.y); lo[1] = __float2half(acc.y - __half2float(hi[1]));
    hi[2] = __float2half(acc.z); lo[2] = __float2half(acc.z - __half2float(hi[2]));
    hi[3] = __float2half(acc.w); lo[3] = __float2half(acc.w - __half2float(hi[3]));
    *(uint2*)(g_hh_hi + w * H + c4) = *(uint2*)hi;
    *(uint2*)(g_hh_lo + w * H + c4) = *(uint2*)lo;
}

// ---------------- pooling + final linear ----------------
__global__ void k_pool(const int* __restrict__ batch) {
    int idx = blockIdx.x * blockDim.x + threadIdx.x;
    if (idx >= NN * H) return;
    int i = idx >> 7, c = idx & (H - 1);
    atomicAdd(&g_pool[batch[i] * H + c], g_h[idx]);
}

__global__ void k_cnt(const int* __restrict__ batch) {
    int i = blockIdx.x * blockDim.x + threadIdx.x;
    if (i < NN) atomicAdd(&g_cnt[batch[i]], 1.f);
}

__global__ void k_final(const float* __restrict__ Wlin, const float* __restrict__ blin,
                        float* __restrict__ out) {
    __shared__ float p[H];
    int g = blockIdx.x, j = threadIdx.x;
    float cnt = fmaxf(g_cnt[g], 1.f);
    p[j] = g_pool[g * H + j] / cnt;
    __syncthreads();
    float s = blin[j];
    #pragma unroll 8
    for (int k = 0; k < H; k++) s = fmaf(p[k], Wlin[k * H + j], s);
    out[g * H + j] = s;
}

// ---------------- launch ----------------
extern "C" void kernel_launch(void* const* d_in, const int* in_sizes, int n_in,
                              void* d_out, int out_size) {
    const int*   x     = (const int*)d_in[0];
    const int*   ei    = (const int*)d_in[1];
    const float* eattr = (const float*)d_in[2];
    const int*   batch = (const int*)d_in[3];
    const float* emb   = (const float*)d_in[4];
    const float* Wf[3] = {(const float*)d_in[5],  (const float*)d_in[9],  (const float*)d_in[13]};
    const float* bf[3] = {(const float*)d_in[6],  (const float*)d_in[10], (const float*)d_in[14]};
    const float* Ws[3] = {(const float*)d_in[7],  (const float*)d_in[11], (const float*)d_in[15]};
    const float* bs[3] = {(const float*)d_in[8],  (const float*)d_in[12], (const float*)d_in[16]};
    const float* Wlin  = (const float*)d_in[17];
    const float* blin  = (const float*)d_in[18];
    float* out = (float*)d_out;

    static int smem_set = 0;
    if (!smem_set) {
        cudaFuncSetAttribute(gemm_node, cudaFuncAttributeMaxDynamicSharedMemorySize, SM_NODE);
        smem_set = 1;
    }

    // gemm_node at launch index 3 (ncu capture slot) to verify the smem-staging fix
    k_pack<<<(65536 + 8192 + 256 + 255) / 256, 256>>>(Wf[0], bf[0], Ws[0], bs[0]);   // 0
    k_embed<<<(NN * H + 255) / 256, 256>>>(x, emb);                                   // 1
    k_zero<<<(NG * H + 255) / 256, 256>>>();                                          // 2
    gemm_node<<<(NN + 127) / 128, 256, SM_NODE>>>();                                  // 3 <- ncu
    k_count<<<(NE + 255) / 256, 256>>>(ei);                                           // 4
    k_scan1<<<NBLK, 1024>>>();
    k_scan2<<<1, 32>>>();
    k_scan3<<<NBLK, 1024>>>();
    k_scatter<<<(NE + 255) / 256, 256>>>(ei);
    k_econv<<<(NE * 4 + 255) / 256, 256>>>(eattr);
    gemm_edge<<<NE / 64, 256>>>();
    k_edge<<<(NN * 32 + 255) / 256, 256>>>();

    for (int l = 1; l < 3; l++) {
        k_pack<<<(65536 + 8192 + 256 + 255) / 256, 256>>>(Wf[l], bf[l], Ws[l], bs[l]);
        gemm_node<<<(NN + 127) / 128, 256, SM_NODE>>>();
        gemm_edge<<<NE / 64, 256>>>();
        k_edge<<<(NN * 32 + 255) / 256, 256>>>();
    }

    k_pool<<<(NN * H + 255) / 256, 256>>>(batch);
    k_cnt<<<(NN + 255) / 256, 256>>>(batch);
    k_final<<<NG, H>>>(Wlin, blin, out);
}